// round 8
// baseline (speedup 1.0000x reference)
#include <cuda_runtime.h>
#include <cuda_bf16.h>
#include <math.h>
#include <stdint.h>

// Problem constants
#define BB 4
#define SS 2048
#define EE 1024
#define HH 16
#define HD 64
#define MROWS (BB * SS)        // 8192
#define QKVN  (3 * EE)         // 3072
#define KSPLIT (3 * EE)        // split-K' = 3072

// GEMM config: CTA 128x128, BK=32 bf16, 8 warps (4Mx2N), warp tile 32x64
#define BKI 32
#define NSTG 3
#define ROWPITCH 80
#define ATILE_B (128 * ROWPITCH)
#define STG_B   (2 * ATILE_B)
#define GEMM_SMEM (NSTG * STG_B)

// Attention config: k-tile 64 keys, rows padded to 144B
#define AT_ROWP 144
#define AT_TILE_B (64 * AT_ROWP)
#define AT_STG_B (4 * AT_TILE_B)
#define AT_NSTG 3
#define ATT_SMEM (AT_NSTG * AT_STG_B)

// Scratch (static device globals)
__device__ __nv_bfloat16  g_a1[MROWS * KSPLIT];    // x split
__device__ __nv_bfloat16  g_b1[QKVN  * KSPLIT];    // qkv_w split
__device__ __nv_bfloat16  g_a2[MROWS * KSPLIT];    // attn out split (written by attn)
__device__ __nv_bfloat16  g_b2[EE    * KSPLIT];    // out_w split
// per-head attention operands [B*H, S, 64]
__device__ __nv_bfloat16  g_Qh[BB * HH * SS * HD];
__device__ __nv_bfloat16  g_Ql[BB * HH * SS * HD];
__device__ __nv_bfloat16  g_Kh[BB * HH * SS * HD];
__device__ __nv_bfloat16  g_Kl[BB * HH * SS * HD];
__device__ __nv_bfloat16  g_Vh[BB * HH * SS * HD];
__device__ __nv_bfloat16  g_Vl[BB * HH * SS * HD];

// ---------------------------------------------------------------------------
// PTX helpers
// ---------------------------------------------------------------------------
__device__ __forceinline__ uint32_t smem_u32(const void* p) {
    uint32_t a;
    asm("{ .reg .u64 t; cvta.to.shared.u64 t, %1; cvt.u32.u64 %0, t; }" : "=r"(a) : "l"(p));
    return a;
}
__device__ __forceinline__ void cp_async16(uint32_t dst, const void* src) {
    asm volatile("cp.async.cg.shared.global [%0], [%1], 16;" :: "r"(dst), "l"(src));
}
__device__ __forceinline__ void cp_commit() {
    asm volatile("cp.async.commit_group;");
}
template<int N>
__device__ __forceinline__ void cp_wait() {
    asm volatile("cp.async.wait_group %0;" :: "n"(N));
}
__device__ __forceinline__ void ldmx4(uint32_t* r, uint32_t addr) {
    asm volatile("ldmatrix.sync.aligned.m8n8.x4.shared.b16 {%0,%1,%2,%3}, [%4];"
        : "=r"(r[0]), "=r"(r[1]), "=r"(r[2]), "=r"(r[3]) : "r"(addr));
}
__device__ __forceinline__ void ldmx4t(uint32_t* r, uint32_t addr) {
    asm volatile("ldmatrix.sync.aligned.m8n8.x4.trans.shared.b16 {%0,%1,%2,%3}, [%4];"
        : "=r"(r[0]), "=r"(r[1]), "=r"(r[2]), "=r"(r[3]) : "r"(addr));
}
__device__ __forceinline__ void mma16816(float* d, const uint32_t* a, const uint32_t* b) {
    asm volatile(
        "mma.sync.aligned.m16n8k16.row.col.f32.bf16.bf16.f32 "
        "{%0,%1,%2,%3}, {%4,%5,%6,%7}, {%8,%9}, {%0,%1,%2,%3};"
        : "+f"(d[0]), "+f"(d[1]), "+f"(d[2]), "+f"(d[3])
        : "r"(a[0]), "r"(a[1]), "r"(a[2]), "r"(a[3]), "r"(b[0]), "r"(b[1]));
}
__device__ __forceinline__ uint32_t pack_bf2(float a, float b) {
    __nv_bfloat162 t;
    t.x = __float2bfloat16_rn(a);
    t.y = __float2bfloat16_rn(b);
    return *reinterpret_cast<uint32_t*>(&t);
}
// hi/lo split of a float2 -> two packed uint32
__device__ __forceinline__ void split2(float x, float y, uint32_t& hi, uint32_t& lo) {
    float hx = __bfloat162float(__float2bfloat16_rn(x));
    float hy = __bfloat162float(__float2bfloat16_rn(y));
    hi = pack_bf2(hx, hy);
    lo = pack_bf2(x - hx, y - hy);
}

// ---------------------------------------------------------------------------
// Split prep: fp32 -> bf16 [hi|lo|hi] (A) or [hi|hi|lo] (B); dst [rows, 3K]
// ---------------------------------------------------------------------------
template<int PATTERN>
__global__ __launch_bounds__(256) void split_kernel(
    const float* __restrict__ src, __nv_bfloat16* __restrict__ dst, int K)
{
    const int idx = blockIdx.x * 256 + threadIdx.x;
    const int pairsPerRow = K >> 1;
    const int m = idx / pairsPerRow;
    const int k = (idx - m * pairsPerRow) << 1;
    const float2 v = *reinterpret_cast<const float2*>(src + (size_t)m * K + k);
    uint32_t hi, lo;
    split2(v.x, v.y, hi, lo);
    uint32_t* base = reinterpret_cast<uint32_t*>(dst + (size_t)m * 3 * K);
    const int kp = k >> 1;
    if (PATTERN == 0) { base[kp] = hi; base[(K >> 1) + kp] = lo; base[K + kp] = hi; }
    else              { base[kp] = hi; base[(K >> 1) + kp] = hi; base[K + kp] = lo; }
}

// ---------------------------------------------------------------------------
// bf16 mma.sync GEMM core (proven mainloop) + two epilogues:
//   MODE 0: C = fp32, + bias
//   MODE 1: direct per-head hi/lo split into Qh/Ql/Kh/Kl/Vh/Vl (Q scaled 1/8)
// ---------------------------------------------------------------------------
__device__ __forceinline__ void load_stage(
    uint32_t sstage, const __nv_bfloat16* __restrict__ A,
    const __nv_bfloat16* __restrict__ B,
    int bm, int bn, int k0, int Kel, int tid)
{
    #pragma unroll
    for (int i = 0; i < 2; ++i) {
        const int idx = tid + i * 256;
        const int row = idx >> 2, ch = idx & 3;
        cp_async16(sstage + row * ROWPITCH + ch * 16,
                   A + (size_t)(bm + row) * Kel + k0 + ch * 8);
        cp_async16(sstage + ATILE_B + row * ROWPITCH + ch * 16,
                   B + (size_t)(bn + row) * Kel + k0 + ch * 8);
    }
}

template<int MODE>
__global__ __launch_bounds__(256) void gemm_mma(
    const __nv_bfloat16* __restrict__ A, const __nv_bfloat16* __restrict__ B,
    const float* __restrict__ bias, float* __restrict__ C,
    __nv_bfloat16* __restrict__ Qh, __nv_bfloat16* __restrict__ Ql,
    __nv_bfloat16* __restrict__ Kh, __nv_bfloat16* __restrict__ Kl,
    __nv_bfloat16* __restrict__ Vh, __nv_bfloat16* __restrict__ Vl,
    int N, int Kel)
{
    extern __shared__ __align__(128) char smem[];
    const uint32_t sb = smem_u32(smem);
    const int tid  = threadIdx.x;
    const int lane = tid & 31;
    const int wid  = tid >> 5;
    const int wm   = wid >> 1;
    const int wn   = wid & 1;
    const int bm = blockIdx.y * 128;
    const int bn = blockIdx.x * 128;
    const int kIters = Kel / BKI;

    uint32_t aOff[2];
    {
        const int arow = wm * 32 + (lane & 15);
        #pragma unroll
        for (int t = 0; t < 2; ++t)
            aOff[t] = (uint32_t)((arow + t * 16) * ROWPITCH + (lane >> 4) * 16);
    }
    uint32_t bOff[4];
    {
        #pragma unroll
        for (int p = 0; p < 4; ++p) {
            const int brow = wn * 64 + p * 16 + (lane & 7) + ((lane >> 4) & 1) * 8;
            bOff[p] = (uint32_t)(ATILE_B + brow * ROWPITCH + ((lane >> 3) & 1) * 16);
        }
    }

    float acc[2][8][4];
    #pragma unroll
    for (int mt = 0; mt < 2; ++mt)
        #pragma unroll
        for (int nt = 0; nt < 8; ++nt)
            #pragma unroll
            for (int r = 0; r < 4; ++r) acc[mt][nt][r] = 0.0f;

    #pragma unroll
    for (int s = 0; s < NSTG - 1; ++s) {
        load_stage(sb + s * STG_B, A, B, bm, bn, s * BKI, Kel, tid);
        cp_commit();
    }
    cp_wait<NSTG - 2>();
    __syncthreads();

    int cur = 0;
    for (int i = 0; i < kIters; ++i) {
        if (i + NSTG - 1 < kIters) {
            const int s = (cur + NSTG - 1) % NSTG;
            load_stage(sb + s * STG_B, A, B, bm, bn, (i + NSTG - 1) * BKI, Kel, tid);
        }
        cp_commit();

        const uint32_t st = sb + cur * STG_B;
        #pragma unroll
        for (int kb = 0; kb < 2; ++kb) {
            uint32_t a[2][4], br[8][2];
            #pragma unroll
            for (int t = 0; t < 2; ++t)
                ldmx4(a[t], st + aOff[t] + kb * 32);
            #pragma unroll
            for (int p = 0; p < 4; ++p) {
                uint32_t r[4];
                ldmx4(r, st + bOff[p] + kb * 32);
                br[p * 2 + 0][0] = r[0]; br[p * 2 + 0][1] = r[1];
                br[p * 2 + 1][0] = r[2]; br[p * 2 + 1][1] = r[3];
            }
            #pragma unroll
            for (int mt = 0; mt < 2; ++mt)
                #pragma unroll
                for (int nt = 0; nt < 8; ++nt)
                    mma16816(acc[mt][nt], a[mt], br[nt]);
        }

        cp_wait<NSTG - 2>();
        __syncthreads();
        cur = (cur + 1) % NSTG;
    }

    const int g  = lane >> 2;
    const int tq = lane & 3;

    if (MODE == 0) {
        // fp32 output + bias
        #pragma unroll
        for (int mt = 0; mt < 2; ++mt) {
            #pragma unroll
            for (int rh = 0; rh < 2; ++rh) {
                const int row = bm + wm * 32 + mt * 16 + g + rh * 8;
                float* crow = C + (size_t)row * N;
                #pragma unroll
                for (int nt = 0; nt < 8; ++nt) {
                    const int col = bn + wn * 64 + nt * 8 + tq * 2;
                    float2 bs = *reinterpret_cast<const float2*>(bias + col);
                    float2 o;
                    o.x = acc[mt][nt][rh * 2 + 0] + bs.x;
                    o.y = acc[mt][nt][rh * 2 + 1] + bs.y;
                    *reinterpret_cast<float2*>(crow + col) = o;
                }
            }
        }
    } else {
        // fused per-head split epilogue: col -> (h, part, d); Q scaled by 1/8
        #pragma unroll
        for (int mt = 0; mt < 2; ++mt) {
            #pragma unroll
            for (int rh = 0; rh < 2; ++rh) {
                const int row = bm + wm * 32 + mt * 16 + g + rh * 8;
                const int b = row >> 11;            // / SS
                const int s = row & (SS - 1);
                #pragma unroll
                for (int nt = 0; nt < 8; ++nt) {
                    const int col = bn + wn * 64 + nt * 8 + tq * 2;
                    const int h = col / 192;
                    const int rem = col - h * 192;
                    const int part = rem >> 6;
                    const int d = rem & 63;
                    float2 bs = *reinterpret_cast<const float2*>(bias + col);
                    float vx = acc[mt][nt][rh * 2 + 0] + bs.x;
                    float vy = acc[mt][nt][rh * 2 + 1] + bs.y;
                    if (part == 0) { vx *= 0.125f; vy *= 0.125f; }
                    uint32_t hi, lo;
                    split2(vx, vy, hi, lo);
                    __nv_bfloat16* dh = (part == 0) ? Qh : (part == 1) ? Kh : Vh;
                    __nv_bfloat16* dl = (part == 0) ? Ql : (part == 1) ? Kl : Vl;
                    const size_t o = (((size_t)(b * HH + h)) * SS + s) * HD + d;
                    *reinterpret_cast<uint32_t*>(dh + o) = hi;
                    *reinterpret_cast<uint32_t*>(dl + o) = lo;
                }
            }
        }
    }
}

// ---------------------------------------------------------------------------
// Tensor-core flash attention (causal), fused [hi|lo|hi] split epilogue.
// ---------------------------------------------------------------------------
__device__ __forceinline__ void load_att_stage(
    uint32_t dst, const __nv_bfloat16* __restrict__ Kh,
    const __nv_bfloat16* __restrict__ Kl,
    const __nv_bfloat16* __restrict__ Vh,
    const __nv_bfloat16* __restrict__ Vl,
    int bh, int key0, int tid)
{
    const int rr = tid >> 3;
    const int cc = tid & 7;
    const size_t src0 = ((size_t)bh * SS + key0 + rr) * HD + cc * 8;
    const size_t src1 = src0 + 32 * HD;
    const uint32_t d0 = dst + rr * AT_ROWP + cc * 16;
    const uint32_t d1 = d0 + 32 * AT_ROWP;
    cp_async16(d0,                  Kh + src0);
    cp_async16(d1,                  Kh + src1);
    cp_async16(d0 + AT_TILE_B,      Kl + src0);
    cp_async16(d1 + AT_TILE_B,      Kl + src1);
    cp_async16(d0 + 2 * AT_TILE_B,  Vh + src0);
    cp_async16(d1 + 2 * AT_TILE_B,  Vh + src1);
    cp_async16(d0 + 3 * AT_TILE_B,  Vl + src0);
    cp_async16(d1 + 3 * AT_TILE_B,  Vl + src1);
}

__global__ __launch_bounds__(256, 1) void attn_mma(
    const __nv_bfloat16* __restrict__ Qh, const __nv_bfloat16* __restrict__ Ql,
    const __nv_bfloat16* __restrict__ Kh, const __nv_bfloat16* __restrict__ Kl,
    const __nv_bfloat16* __restrict__ Vh, const __nv_bfloat16* __restrict__ Vl,
    __nv_bfloat16* __restrict__ a2out)
{
    extern __shared__ __align__(128) char smem[];
    const uint32_t sb = smem_u32(smem);
    const int tid  = threadIdx.x;
    const int lane = tid & 31;
    const int w    = tid >> 5;
    const int g    = lane >> 2;
    const int tq   = lane & 3;

    const int qt = (gridDim.x - 1) - blockIdx.x;
    const int h  = blockIdx.y;
    const int b  = blockIdx.z;
    const int bh = b * HH + h;
    const int qbase = qt * 128;
    const int nkt = 2 * qt + 2;

    uint32_t qah[4][4], qal[4][4];
    {
        const __nv_bfloat16* qh0 = Qh + ((size_t)bh * SS + qbase + w * 16) * HD;
        const __nv_bfloat16* ql0 = Ql + ((size_t)bh * SS + qbase + w * 16) * HD;
        #pragma unroll
        for (int kc = 0; kc < 4; ++kc) {
            const int c0 = kc * 16 + tq * 2;
            qah[kc][0] = *reinterpret_cast<const uint32_t*>(qh0 + g * HD + c0);
            qah[kc][1] = *reinterpret_cast<const uint32_t*>(qh0 + (g + 8) * HD + c0);
            qah[kc][2] = *reinterpret_cast<const uint32_t*>(qh0 + g * HD + c0 + 8);
            qah[kc][3] = *reinterpret_cast<const uint32_t*>(qh0 + (g + 8) * HD + c0 + 8);
            qal[kc][0] = *reinterpret_cast<const uint32_t*>(ql0 + g * HD + c0);
            qal[kc][1] = *reinterpret_cast<const uint32_t*>(ql0 + (g + 8) * HD + c0);
            qal[kc][2] = *reinterpret_cast<const uint32_t*>(ql0 + g * HD + c0 + 8);
            qal[kc][3] = *reinterpret_cast<const uint32_t*>(ql0 + (g + 8) * HD + c0 + 8);
        }
    }

    float m0 = -1e30f, m1 = -1e30f, l0 = 0.0f, l1 = 0.0f;
    float O[8][4];
    #pragma unroll
    for (int nf = 0; nf < 8; ++nf)
        #pragma unroll
        for (int e = 0; e < 4; ++e) O[nf][e] = 0.0f;

    uint32_t koff[4];
    #pragma unroll
    for (int np = 0; np < 4; ++np)
        koff[np] = (uint32_t)((np * 16 + (lane & 7) + ((lane >> 4) & 1) * 8) * AT_ROWP
                              + ((lane >> 3) & 1) * 16);
    uint32_t voff[4][4];
    #pragma unroll
    for (int kc2 = 0; kc2 < 4; ++kc2)
        #pragma unroll
        for (int np = 0; np < 4; ++np)
            voff[kc2][np] = (uint32_t)((kc2 * 16 + (lane & 7) + ((lane >> 3) & 1) * 8) * AT_ROWP
                                       + (np * 16 + ((lane >> 4) & 1) * 8) * 2);

    load_att_stage(sb, Kh, Kl, Vh, Vl, bh, 0, tid);
    cp_commit();
    load_att_stage(sb + AT_STG_B, Kh, Kl, Vh, Vl, bh, 64, tid);
    cp_commit();
    cp_wait<1>();
    __syncthreads();

    int cur = 0;
    for (int kt = 0; kt < nkt; ++kt) {
        if (kt + 2 < nkt) {
            load_att_stage(sb + ((cur + 2) % AT_NSTG) * AT_STG_B,
                           Kh, Kl, Vh, Vl, bh, (kt + 2) * 64, tid);
        }
        cp_commit();

        const uint32_t st = sb + cur * AT_STG_B;

        float sacc[8][4];
        #pragma unroll
        for (int nf = 0; nf < 8; ++nf)
            #pragma unroll
            for (int e = 0; e < 4; ++e) sacc[nf][e] = 0.0f;

        #pragma unroll
        for (int kc = 0; kc < 4; ++kc) {
            #pragma unroll
            for (int np = 0; np < 4; ++np) {
                uint32_t kh[4], kl[4];
                ldmx4(kh, st + koff[np] + kc * 32);
                ldmx4(kl, st + AT_TILE_B + koff[np] + kc * 32);
                mma16816(sacc[2 * np],     qah[kc], kh);
                mma16816(sacc[2 * np],     qal[kc], kh);
                mma16816(sacc[2 * np],     qah[kc], kl);
                mma16816(sacc[2 * np + 1], qah[kc], kh + 2);
                mma16816(sacc[2 * np + 1], qal[kc], kh + 2);
                mma16816(sacc[2 * np + 1], qah[kc], kl + 2);
            }
        }

        if (kt >= 2 * qt) {
            const int key0 = kt * 64;
            const int r0 = qbase + w * 16 + g;
            #pragma unroll
            for (int nf = 0; nf < 8; ++nf) {
                const int c0 = key0 + nf * 8 + tq * 2;
                if (c0     > r0)     sacc[nf][0] = -1e30f;
                if (c0 + 1 > r0)     sacc[nf][1] = -1e30f;
                if (c0     > r0 + 8) sacc[nf][2] = -1e30f;
                if (c0 + 1 > r0 + 8) sacc[nf][3] = -1e30f;
            }
        }

        float tm0 = -1e30f, tm1 = -1e30f;
        #pragma unroll
        for (int nf = 0; nf < 8; ++nf) {
            tm0 = fmaxf(tm0, fmaxf(sacc[nf][0], sacc[nf][1]));
            tm1 = fmaxf(tm1, fmaxf(sacc[nf][2], sacc[nf][3]));
        }
        tm0 = fmaxf(tm0, __shfl_xor_sync(0xffffffffu, tm0, 1));
        tm0 = fmaxf(tm0, __shfl_xor_sync(0xffffffffu, tm0, 2));
        tm1 = fmaxf(tm1, __shfl_xor_sync(0xffffffffu, tm1, 1));
        tm1 = fmaxf(tm1, __shfl_xor_sync(0xffffffffu, tm1, 2));
        const float mn0 = fmaxf(m0, tm0);
        const float mn1 = fmaxf(m1, tm1);
        const float cr0 = __expf(m0 - mn0);
        const float cr1 = __expf(m1 - mn1);
        m0 = mn0; m1 = mn1;

        float rs0 = 0.0f, rs1 = 0.0f;
        uint32_t pah[4][4], pal[4][4];
        #pragma unroll
        for (int nf = 0; nf < 8; ++nf) {
            float p0 = __expf(sacc[nf][0] - mn0);
            float p1 = __expf(sacc[nf][1] - mn0);
            float p2 = __expf(sacc[nf][2] - mn1);
            float p3 = __expf(sacc[nf][3] - mn1);
            rs0 += p0 + p1; rs1 += p2 + p3;
            const int kc2 = nf >> 1;
            const int o = (nf & 1) ? 2 : 0;
            float h0f = __bfloat162float(__float2bfloat16_rn(p0));
            float h1f = __bfloat162float(__float2bfloat16_rn(p1));
            float h2f = __bfloat162float(__float2bfloat16_rn(p2));
            float h3f = __bfloat162float(__float2bfloat16_rn(p3));
            pah[kc2][o]     = pack_bf2(h0f, h1f);
            pah[kc2][o + 1] = pack_bf2(h2f, h3f);
            pal[kc2][o]     = pack_bf2(p0 - h0f, p1 - h1f);
            pal[kc2][o + 1] = pack_bf2(p2 - h2f, p3 - h3f);
        }
        rs0 += __shfl_xor_sync(0xffffffffu, rs0, 1);
        rs0 += __shfl_xor_sync(0xffffffffu, rs0, 2);
        rs1 += __shfl_xor_sync(0xffffffffu, rs1, 1);
        rs1 += __shfl_xor_sync(0xffffffffu, rs1, 2);
        l0 = l0 * cr0 + rs0;
        l1 = l1 * cr1 + rs1;
        #pragma unroll
        for (int nf = 0; nf < 8; ++nf) {
            O[nf][0] *= cr0; O[nf][1] *= cr0;
            O[nf][2] *= cr1; O[nf][3] *= cr1;
        }

        #pragma unroll
        for (int kc2 = 0; kc2 < 4; ++kc2) {
            #pragma unroll
            for (int np = 0; np < 4; ++np) {
                uint32_t vh[4], vl[4];
                ldmx4t(vh, st + 2 * AT_TILE_B + voff[kc2][np]);
                ldmx4t(vl, st + 3 * AT_TILE_B + voff[kc2][np]);
                mma16816(O[2 * np],     pah[kc2], vh);
                mma16816(O[2 * np],     pal[kc2], vh);
                mma16816(O[2 * np],     pah[kc2], vl);
                mma16816(O[2 * np + 1], pah[kc2], vh + 2);
                mma16816(O[2 * np + 1], pal[kc2], vh + 2);
                mma16816(O[2 * np + 1], pah[kc2], vl + 2);
            }
        }

        cp_wait<1>();
        __syncthreads();
        cur = (cur + 1) % AT_NSTG;
    }

    // ---- fused epilogue: write [hi|lo|hi] split rows of a2 directly ----
    const float i0 = 1.0f / l0;
    const float i1 = 1.0f / l1;
    const int r0 = qbase + w * 16 + g;
    __nv_bfloat16* row0 = a2out + (size_t)(b * SS + r0) * KSPLIT;
    __nv_bfloat16* row1 = row0 + (size_t)8 * KSPLIT;
    const int colb = h * HD;
    #pragma unroll
    for (int nf = 0; nf < 8; ++nf) {
        const int col = colb + nf * 8 + tq * 2;
        uint32_t hi, lo;
        split2(O[nf][0] * i0, O[nf][1] * i0, hi, lo);
        *reinterpret_cast<uint32_t*>(row0 + col)        = hi;
        *reinterpret_cast<uint32_t*>(row0 + col + EE)   = lo;
        *reinterpret_cast<uint32_t*>(row0 + col + 2*EE) = hi;
        split2(O[nf][2] * i1, O[nf][3] * i1, hi, lo);
        *reinterpret_cast<uint32_t*>(row1 + col)        = hi;
        *reinterpret_cast<uint32_t*>(row1 + col + EE)   = lo;
        *reinterpret_cast<uint32_t*>(row1 + col + 2*EE) = hi;
    }
}

// ---------------------------------------------------------------------------
// Launch
// ---------------------------------------------------------------------------
extern "C" void kernel_launch(void* const* d_in, const int* in_sizes, int n_in,
                              void* d_out, int out_size)
{
    const float* x      = (const float*)d_in[0];
    const float* qkv_w  = (const float*)d_in[1];
    const float* qkv_b  = (const float*)d_in[2];
    const float* out_w  = (const float*)d_in[3];
    const float* out_b  = (const float*)d_in[4];
    float* out = (float*)d_out;

    __nv_bfloat16 *a1, *b1, *a2, *b2, *Qh, *Ql, *Kh, *Kl, *Vh, *Vl;
    cudaGetSymbolAddress((void**)&a1, g_a1);
    cudaGetSymbolAddress((void**)&b1, g_b1);
    cudaGetSymbolAddress((void**)&a2, g_a2);
    cudaGetSymbolAddress((void**)&b2, g_b2);
    cudaGetSymbolAddress((void**)&Qh, g_Qh);
    cudaGetSymbolAddress((void**)&Ql, g_Ql);
    cudaGetSymbolAddress((void**)&Kh, g_Kh);
    cudaGetSymbolAddress((void**)&Kl, g_Kl);
    cudaGetSymbolAddress((void**)&Vh, g_Vh);
    cudaGetSymbolAddress((void**)&Vl, g_Vl);

    cudaFuncSetAttribute(gemm_mma<0>, cudaFuncAttributeMaxDynamicSharedMemorySize, GEMM_SMEM);
    cudaFuncSetAttribute(gemm_mma<1>, cudaFuncAttributeMaxDynamicSharedMemorySize, GEMM_SMEM);
    cudaFuncSetAttribute(attn_mma, cudaFuncAttributeMaxDynamicSharedMemorySize, ATT_SMEM);

    // 1) split prep
    split_kernel<0><<<MROWS * EE / 512, 256>>>(x, a1, EE);
    split_kernel<1><<<QKVN  * EE / 512, 256>>>(qkv_w, b1, EE);
    split_kernel<1><<<EE    * EE / 512, 256>>>(out_w, b2, EE);

    // 2) QKV projection with fused per-head split epilogue
    {
        dim3 grid(QKVN / 128, MROWS / 128);
        gemm_mma<1><<<grid, 256, GEMM_SMEM>>>(a1, b1, qkv_b, nullptr,
                                              Qh, Ql, Kh, Kl, Vh, Vl, QKVN, KSPLIT);
    }

    // 3) tensor-core causal flash attention with fused split epilogue -> a2
    {
        dim3 grid(SS / 128, HH, BB);
        attn_mma<<<grid, 256, ATT_SMEM>>>(Qh, Ql, Kh, Kl, Vh, Vl, a2);
    }

    // 4) Output projection
    {
        dim3 grid(EE / 128, MROWS / 128);
        gemm_mma<0><<<grid, 256, GEMM_SMEM>>>(a2, b2, out_b, out,
                                              nullptr, nullptr, nullptr, nullptr,
                                              nullptr, nullptr, EE, KSPLIT);
    }
}